// round 16
// baseline (speedup 1.0000x reference)
#include <cuda_runtime.h>
#include <cuda_bf16.h>
#include <cstdint>
#include <math.h>

#define Bsz 4
#define Nn 4096
#define DIMc 256
#define Hh 8
#define DHd 64
#define Pp 2
#define INNERc 512
#define MQ (Bsz*Nn)      /* 16384 */
#define MKV (2*Bsz*Nn)   /* 32768 */

typedef __nv_bfloat16 bf16;

// ---------------- scratch (device globals) ----------------
__device__ bf16  g_qlnh[MQ * INNERc];
__device__ bf16  g_qlnl[MQ * INNERc];
__device__ float g_q   [MQ * INNERc];
__device__ bf16  g_nh  [MKV * DIMc];
__device__ bf16  g_nl  [MKV * DIMc];
__device__ float g_kv  [MKV * 2 * INNERc];
__device__ bf16  g_aoh [MQ * INNERc];
__device__ bf16  g_aol [MQ * INNERc];
__device__ bf16  g_wqTh[INNERc * INNERc];
__device__ bf16  g_wqTl[INNERc * INNERc];
__device__ bf16  g_wkvTh[2 * INNERc * DIMc];
__device__ bf16  g_wkvTl[2 * INNERc * DIMc];
__device__ bf16  g_wouth[DIMc * INNERc];
__device__ bf16  g_woutl[DIMc * INNERc];
__device__ float g_biasq [INNERc];
__device__ float g_biaskv[2 * INNERc];
__device__ bf16  g_w2h [64 * INNERc];     // folded offset weights (rows 16..63 zero)
__device__ bf16  g_w2l [64 * INNERc];
__device__ float g_bias2[64];
__device__ float g_offb[MQ * 64];         // offsets GEMM output [row, 64]

// ================= helpers =================
__device__ __forceinline__ uint32_t smem_u32(const void* p){
    uint32_t a;
    asm("{ .reg .u64 t; cvta.to.shared.u64 t, %1; cvt.u32.u64 %0, t; }" : "=r"(a) : "l"(p));
    return a;
}
__device__ __forceinline__ void bsplit(float v, bf16& h, bf16& l){
    h = __float2bfloat16(v);
    l = __float2bfloat16(v - __bfloat162float(h));
}
__device__ __forceinline__ void mma_bf16(float d[4], const uint32_t a[4], const uint32_t b[2]){
    asm volatile("mma.sync.aligned.m16n8k16.row.col.f32.bf16.bf16.f32 "
        "{%0,%1,%2,%3}, {%4,%5,%6,%7}, {%8,%9}, {%0,%1,%2,%3};"
        : "+f"(d[0]),"+f"(d[1]),"+f"(d[2]),"+f"(d[3])
        : "r"(a[0]),"r"(a[1]),"r"(a[2]),"r"(a[3]),"r"(b[0]),"r"(b[1]));
}
__device__ __forceinline__ void ldsm4(uint32_t r[4], uint32_t addr){
    asm volatile("ldmatrix.sync.aligned.m8n8.x4.shared.b16 {%0,%1,%2,%3}, [%4];"
        : "=r"(r[0]),"=r"(r[1]),"=r"(r[2]),"=r"(r[3]) : "r"(addr));
}
__device__ __forceinline__ void cp16(uint32_t dst, const void* src){
    asm volatile("cp.async.cg.shared.global [%0], [%1], 16;" :: "r"(dst), "l"(src));
}
__device__ __forceinline__ uint32_t swz(int r, int s){
    return (uint32_t)(r * 64 + ((s ^ ((r >> 1) & 3)) << 4));
}

// ================= bf16x3 tensor-core GEMM =================
#define TILE_A 8192

template<int HAS_BIAS, int NT>
__global__ void __launch_bounds__(256, 2)
bf16x3_gemm(const bf16* __restrict__ Ah, const bf16* __restrict__ Al,
            const bf16* __restrict__ Bh, const bf16* __restrict__ Bl,
            const float* __restrict__ bias, float* __restrict__ C,
            int Ntot, int K)
{
    cudaGridDependencySynchronize();
    constexpr int NJ  = NT / 32;
    constexpr int NJP = NT / 64;
    constexpr int TILE_BP = NT * 64;
    constexpr int STAGE = 2*TILE_A + 2*TILE_BP;

    extern __shared__ char smem[];
    const uint32_t sb = smem_u32(smem);
    const int tid = threadIdx.x, lane = tid & 31, wid = tid >> 5;
    const int wm = wid >> 2, wn = wid & 3;
    const int bm = blockIdx.y * 128, bn = blockIdx.x * NT;
    const int NC = K >> 5;

    const int lr  = tid >> 2;
    const int lcc = tid & 3;
    const uint32_t w0 = swz(lr, lcc), w1 = swz(lr + 64, lcc);

    const size_t row64 = (size_t)64 * K;
    const bf16* pAh = Ah + (size_t)(bm + lr) * K + lcc * 8;
    const bf16* pAl = Al + (size_t)(bm + lr) * K + lcc * 8;
    const bf16* pBh = Bh + (size_t)(bn + lr) * K + lcc * 8;
    const bf16* pBl = Bl + (size_t)(bn + lr) * K + lcc * 8;

    uint32_t aoff[2][4], boff[2][NJP];
    #pragma unroll
    for (int ks = 0; ks < 2; ks++){
        const int slot = (lane >> 4) + ks * 2;
        #pragma unroll
        for (int i = 0; i < 4; i++)
            aoff[ks][i] = swz(wm*64 + i*16 + (lane & 15), slot);
        #pragma unroll
        for (int jp = 0; jp < NJP; jp++)
            boff[ks][jp] = 2*TILE_A + swz(wn*(NT/4) + jp*16 + (lane & 15), slot);
    }

    auto load_stage = [&](int buf, int kc){
        uint32_t base = sb + buf * STAGE;
        cp16(base + w0,           pAh + kc);
        cp16(base + w1,           pAh + kc + row64);
        cp16(base + TILE_A + w0,  pAl + kc);
        cp16(base + TILE_A + w1,  pAl + kc + row64);
        cp16(base + 2*TILE_A + w0,            pBh + kc);
        cp16(base + 2*TILE_A + TILE_BP + w0,  pBl + kc);
        if (NT == 128){
            cp16(base + 2*TILE_A + w1,           pBh + kc + row64);
            cp16(base + 2*TILE_A + TILE_BP + w1, pBl + kc + row64);
        }
        asm volatile("cp.async.commit_group;" ::: "memory");
    };

    float acc[4][NJ][4] = {};

    auto compute = [&](int buf){
        uint32_t base = sb + buf * STAGE;
        #pragma unroll
        for (int ks = 0; ks < 2; ks++){
            uint32_t BH[NJ][2], BL[NJ][2];
            #pragma unroll
            for (int jp = 0; jp < NJP; jp++){
                uint32_t a = base + boff[ks][jp];
                uint32_t r4[4];
                ldsm4(r4, a);
                BH[jp*2][0]=r4[0]; BH[jp*2+1][0]=r4[1]; BH[jp*2][1]=r4[2]; BH[jp*2+1][1]=r4[3];
                ldsm4(r4, a + TILE_BP);
                BL[jp*2][0]=r4[0]; BL[jp*2+1][0]=r4[1]; BL[jp*2][1]=r4[2]; BL[jp*2+1][1]=r4[3];
            }
            #pragma unroll
            for (int i = 0; i < 4; i++){
                uint32_t a = base + aoff[ks][i];
                uint32_t ah[4], al_[4];
                ldsm4(ah,  a);
                ldsm4(al_, a + TILE_A);
                #pragma unroll
                for (int j = 0; j < NJ; j++) mma_bf16(acc[i][j], ah,  BH[j]);
                #pragma unroll
                for (int j = 0; j < NJ; j++) mma_bf16(acc[i][j], ah,  BL[j]);
                #pragma unroll
                for (int j = 0; j < NJ; j++) mma_bf16(acc[i][j], al_, BH[j]);
            }
        }
    };

    load_stage(0, 0);
    load_stage(1, 32);

    for (int c = 0; c < NC; c++){
        if (c < NC - 1) asm volatile("cp.async.wait_group 1;" ::: "memory");
        else            asm volatile("cp.async.wait_group 0;" ::: "memory");
        __syncthreads();
        compute(c % 3);
        if (c + 2 < NC) load_stage((c + 2) % 3, (c + 2) * 32);
    }

    #pragma unroll
    for (int i = 0; i < 4; i++){
        int r0 = bm + wm*64 + i*16 + (lane >> 2);
        #pragma unroll
        for (int j = 0; j < NJ; j++){
            int c0 = bn + wn*(NT/4) + j*8 + (lane & 3)*2;
            float b0 = 0.f, b1 = 0.f;
            if (HAS_BIAS){ b0 = bias[c0]; b1 = bias[c0+1]; }
            *(float2*)(C + (size_t)r0 * Ntot + c0)     = make_float2(acc[i][j][0]+b0, acc[i][j][1]+b1);
            *(float2*)(C + (size_t)(r0+8) * Ntot + c0) = make_float2(acc[i][j][2]+b0, acc[i][j][3]+b1);
        }
    }
}

#define GEMM_SMEM_128 (3*(2*TILE_A + 2*128*64))
#define GEMM_SMEM_64  (3*(2*TILE_A + 2*64*64))

// ================= merged prep + LN kernel =================
#define LN_BLOCKS ((MQ + MKV)/8)   /* 6144 */

__device__ __forceinline__ void tss_body(const float* in, const float* g,
                                         bf16* oh, bf16* ol, int R, int C,
                                         int bx, int by, int tx, int ty){
    __shared__ float tile[32][33];
    int c0 = bx * 32, r0 = by * 32;
    #pragma unroll
    for (int i = 0; i < 32; i += 8){
        int r = r0 + ty + i;
        tile[ty + i][tx] = in[(size_t)r * C + c0 + tx] * g[r];
    }
    __syncthreads();
    #pragma unroll
    for (int i = 0; i < 32; i += 8){
        float v = tile[tx][ty + i];
        bf16 h, l; bsplit(v, h, l);
        size_t o = (size_t)(c0 + ty + i) * R + r0 + tx;
        oh[o] = h; ol[o] = l;
    }
}
__device__ __forceinline__ void fold_body(const float* W, const float* beta,
                                          const float* base, float* out,
                                          int K, int N, int n, int lane){
    float s = 0.f;
    for (int k = lane; k < K; k += 32) s += beta[k] * W[(size_t)k * N + n];
    #pragma unroll
    for (int o = 16; o > 0; o >>= 1) s += __shfl_xor_sync(0xffffffffu, s, o);
    if (lane == 0) out[n] = s + (base ? base[n] : 0.f);
}

__global__ void prep_ln_kernel(const float* __restrict__ x, const float* __restrict__ px,
                               const float* __restrict__ Wq, const float* __restrict__ lnqg, const float* __restrict__ lnqb,
                               const float* __restrict__ Wk, const float* __restrict__ lnkg, const float* __restrict__ lnkb, const float* __restrict__ bk,
                               const float* __restrict__ Wv, const float* __restrict__ lnvg, const float* __restrict__ lnvb, const float* __restrict__ bv,
                               const float* __restrict__ Wout,
                               bf16* __restrict__ qoh, bf16* __restrict__ qol,
                               bf16* __restrict__ nh, bf16* __restrict__ nl,
                               bf16* __restrict__ wqTh, bf16* __restrict__ wqTl,
                               bf16* __restrict__ wkvTh, bf16* __restrict__ wkvTl,
                               bf16* __restrict__ wouth, bf16* __restrict__ woutl,
                               float* __restrict__ biasq, float* __restrict__ biaskv){
    cudaGridDependencySynchronize();
    int id = blockIdx.x;
    int tid = threadIdx.x;
    if (id < LN_BLOCKS){
        int gw = id * 8 + (tid >> 5);
        int lane = tid & 31;
        if (gw < MQ){
            size_t base = (size_t)gw * DIMc + lane * 8;
            float4 a0 = *(const float4*)(x  + base);
            float4 a1 = *(const float4*)(x  + base + 4);
            float4 b0 = *(const float4*)(px + base);
            float4 b1 = *(const float4*)(px + base + 4);
            float va[8] = {a0.x,a0.y,a0.z,a0.w,a1.x,a1.y,a1.z,a1.w};
            float vb[8] = {b0.x,b0.y,b0.z,b0.w,b1.x,b1.y,b1.z,b1.w};
            float s = 0.f, ss = 0.f;
            #pragma unroll
            for (int i = 0; i < 8; i++){ s += va[i] + vb[i]; ss += va[i]*va[i] + vb[i]*vb[i]; }
            #pragma unroll
            for (int o = 16; o > 0; o >>= 1){
                s  += __shfl_xor_sync(0xffffffffu, s, o);
                ss += __shfl_xor_sync(0xffffffffu, ss, o);
            }
            float mean = s * (1.0f/512.0f);
            float var  = ss * (1.0f/512.0f) - mean*mean;
            float rstd = rsqrtf(var + 1e-5f);
            uint32_t ph[4], pl[4];
            #pragma unroll
            for (int i = 0; i < 4; i++){
                bf16 h0,l0,h1,l1;
                bsplit((va[2*i]   - mean)*rstd, h0, l0);
                bsplit((va[2*i+1] - mean)*rstd, h1, l1);
                ph[i] = (uint32_t)__bfloat16_as_ushort(h0) | ((uint32_t)__bfloat16_as_ushort(h1) << 16);
                pl[i] = (uint32_t)__bfloat16_as_ushort(l0) | ((uint32_t)__bfloat16_as_ushort(l1) << 16);
            }
            size_t ob = (size_t)gw * INNERc + lane * 8;
            *(uint4*)(qoh + ob) = make_uint4(ph[0],ph[1],ph[2],ph[3]);
            *(uint4*)(qol + ob) = make_uint4(pl[0],pl[1],pl[2],pl[3]);
            #pragma unroll
            for (int i = 0; i < 4; i++){
                bf16 h0,l0,h1,l1;
                bsplit((vb[2*i]   - mean)*rstd, h0, l0);
                bsplit((vb[2*i+1] - mean)*rstd, h1, l1);
                ph[i] = (uint32_t)__bfloat16_as_ushort(h0) | ((uint32_t)__bfloat16_as_ushort(h1) << 16);
                pl[i] = (uint32_t)__bfloat16_as_ushort(l0) | ((uint32_t)__bfloat16_as_ushort(l1) << 16);
            }
            *(uint4*)(qoh + ob + 256) = make_uint4(ph[0],ph[1],ph[2],ph[3]);
            *(uint4*)(qol + ob + 256) = make_uint4(pl[0],pl[1],pl[2],pl[3]);
        } else {
            int row = gw - MQ;
            const float* src = (row < MQ) ? x : px;
            int r2 = (row < MQ) ? row : row - MQ;
            size_t base = (size_t)r2 * DIMc + lane * 8;
            float4 a0 = *(const float4*)(src + base);
            float4 a1 = *(const float4*)(src + base + 4);
            float v[8] = {a0.x,a0.y,a0.z,a0.w,a1.x,a1.y,a1.z,a1.w};
            float s = 0.f, ss = 0.f;
            #pragma unroll
            for (int i = 0; i < 8; i++){ s += v[i]; ss += v[i]*v[i]; }
            #pragma unroll
            for (int o = 16; o > 0; o >>= 1){
                s  += __shfl_xor_sync(0xffffffffu, s, o);
                ss += __shfl_xor_sync(0xffffffffu, ss, o);
            }
            float mean = s * (1.0f/256.0f);
            float var  = ss * (1.0f/256.0f) - mean*mean;
            float rstd = rsqrtf(var + 1e-5f);
            uint32_t ph[4], pl[4];
            #pragma unroll
            for (int i = 0; i < 4; i++){
                bf16 h0,l0,h1,l1;
                bsplit((v[2*i]   - mean)*rstd, h0, l0);
                bsplit((v[2*i+1] - mean)*rstd, h1, l1);
                ph[i] = (uint32_t)__bfloat16_as_ushort(h0) | ((uint32_t)__bfloat16_as_ushort(h1) << 16);
                pl[i] = (uint32_t)__bfloat16_as_ushort(l0) | ((uint32_t)__bfloat16_as_ushort(l1) << 16);
            }
            size_t ob = (size_t)row * DIMc + lane * 8;
            *(uint4*)(nh + ob) = make_uint4(ph[0],ph[1],ph[2],ph[3]);
            *(uint4*)(nl + ob) = make_uint4(pl[0],pl[1],pl[2],pl[3]);
        }
        return;
    }
    int pid = id - LN_BLOCKS;
    int tx = tid & 31, ty = tid >> 5;
    if (pid < 256){
        tss_body(Wq, lnqg, wqTh, wqTl, INNERc, INNERc, pid & 15, pid >> 4, tx, ty);
    } else if (pid < 384){
        int l = pid - 256;
        tss_body(Wk, lnkg, wkvTh, wkvTl, DIMc, INNERc, l & 15, l >> 4, tx, ty);
    } else if (pid < 512){
        int l = pid - 384;
        tss_body(Wv, lnvg, wkvTh + (size_t)INNERc*DIMc, wkvTl + (size_t)INNERc*DIMc,
                 DIMc, INNERc, l & 15, l >> 4, tx, ty);
    } else if (pid < 1024){
        int i = (pid - 512) * 256 + tid;
        bf16 h, l; bsplit(Wout[i], h, l);
        wouth[i] = h; woutl[i] = l;
    } else if (pid < 1088){
        int n = (pid - 1024) * 8 + ty;
        fold_body(Wq, lnqb, nullptr, biasq, INNERc, INNERc, n, tx);
    } else if (pid < 1152){
        int n = (pid - 1088) * 8 + ty;
        fold_body(Wk, lnkb, bk, biaskv, DIMc, INNERc, n, tx);
    } else {
        int n = (pid - 1152) * 8 + ty;
        fold_body(Wv, lnvb, bv, biaskv + INNERc, DIMc, INNERc, n, tx);
    }
}
#define PREP_LN_BLOCKS (LN_BLOCKS + 1216)

// ================= prep2: fold offset weights through Wq =================
// W2[j,m] = lnqg[m] * dot_i(Wq[m,i], Woff[j,i]); bias2[j] = boff[j] + dot_i(biasq, Woff[j,:])
__global__ void prep2_kernel(const float* __restrict__ Wq, const float* __restrict__ lnqg,
                             const float* __restrict__ Woff, const float* __restrict__ boff,
                             const float* __restrict__ biasq,
                             bf16* __restrict__ w2h, bf16* __restrict__ w2l,
                             float* __restrict__ bias2){
    cudaGridDependencySynchronize();
    int id = blockIdx.x;
    int tid = threadIdx.x, lane = tid & 31, wid = tid >> 5;
    if (id < 1024){
        int idx = id * 8 + wid;          // 0..8191
        int j = idx >> 9, m = idx & 511;
        const float* wqr = Wq + (size_t)m * INNERc;
        const float* wor = Woff + (size_t)j * INNERc;
        float s = 0.f;
        for (int i = lane; i < INNERc; i += 32) s += wqr[i] * wor[i];
        #pragma unroll
        for (int o = 16; o > 0; o >>= 1) s += __shfl_xor_sync(0xffffffffu, s, o);
        if (lane == 0){
            bf16 h, l; bsplit(s * lnqg[m], h, l);
            w2h[(size_t)j * INNERc + m] = h;
            w2l[(size_t)j * INNERc + m] = l;
        }
    } else if (id < 1026){
        int j = (id - 1024) * 8 + wid;   // 0..15
        const float* wor = Woff + (size_t)j * INNERc;
        float s = 0.f;
        for (int i = lane; i < INNERc; i += 32) s += biasq[i] * wor[i];
        #pragma unroll
        for (int o = 16; o > 0; o >>= 1) s += __shfl_xor_sync(0xffffffffu, s, o);
        if (lane == 0) bias2[j] = s + boff[j];
    } else {
        int base = (id - 1026) * 256 + tid;       // 0..2047
        bf16 z = __float2bfloat16(0.f);
        for (int e = base; e < 48 * INNERc; e += 2048){
            w2h[16 * INNERc + e] = z;
            w2l[16 * INNERc + e] = z;
        }
        if (id == 1026 && tid < 48) bias2[16 + tid] = 0.f;
    }
}
#define PREP2_BLOCKS 1034

// ================= attention: 2 heads/warp; offsets from GEMM buffer ==========
__global__ void attn_kernel(const float* __restrict__ q, const float* __restrict__ kv,
                            const float* __restrict__ offb,
                            float* __restrict__ out_off,
                            bf16* __restrict__ aoh, bf16* __restrict__ aol) {
    cudaGridDependencySynchronize();
    int gw = (blockIdx.x * blockDim.x + threadIdx.x) >> 5;
    int lane = threadIdx.x & 31;
    if (gw >= MQ * 4) return;
    int bn = gw >> 2;
    int hp = gw & 3;
    int h0 = hp * 2, h1 = hp * 2 + 1;
    int b  = bn / Nn;
    int n  = bn - b * Nn;
    float fn = (float)n;
    const float hi = (float)(2 * Nn - 1);

    float4 offv = *(const float4*)(offb + (size_t)bn * 64 + hp * 4);
    float oA0 = offv.x, oA1 = offv.y, oB0 = offv.z, oB1 = offv.w;

    // write transposed offsets output (B,H,P,N): j = hp*4 + lane
    if (lane < 4){
        float v = (lane == 0) ? offv.x : (lane == 1) ? offv.y : (lane == 2) ? offv.z : offv.w;
        out_off[((size_t)(b * 16 + hp * 4 + lane)) * Nn + n] = v;
    }

    int jA0 = (int)fminf(fmaxf(fn + oA0, 0.f), hi);
    int jA1 = (int)fminf(fmaxf(fn + oA1, 0.f), hi);
    int jB0 = (int)fminf(fmaxf(fn + oB0, 0.f), hi);
    int jB1 = (int)fminf(fmaxf(fn + oB1, 0.f), hi);

    auto rowptr = [&](int j)->const float*{
        int s = (j >= Nn) ? 1 : 0; int np = j - s * Nn;
        return kv + ((size_t)(s * Bsz + b) * Nn + np) * (2*INNERc);
    };
    const float* rA0 = rowptr(jA0) + h0 * DHd;
    const float* rA1 = rowptr(jA1) + h0 * DHd;
    const float* rB0 = rowptr(jB0) + h1 * DHd;
    const float* rB1 = rowptr(jB1) + h1 * DHd;

    const float* qbase = q + (size_t)bn * INNERc;
    float qA0 = qbase[h0*DHd + lane],      qA1 = qbase[h0*DHd + lane + 32];
    float qB0 = qbase[h1*DHd + lane],      qB1 = qbase[h1*DHd + lane + 32];
    float kA0a = rA0[lane], kA0b = rA0[lane+32];
    float kA1a = rA1[lane], kA1b = rA1[lane+32];
    float kB0a = rB0[lane], kB0b = rB0[lane+32];
    float kB1a = rB1[lane], kB1b = rB1[lane+32];
    float vA0a = rA0[INNERc+lane], vA0b = rA0[INNERc+lane+32];
    float vA1a = rA1[INNERc+lane], vA1b = rA1[INNERc+lane+32];
    float vB0a = rB0[INNERc+lane], vB0b = rB0[INNERc+lane+32];
    float vB1a = rB1[INNERc+lane], vB1b = rB1[INNERc+lane+32];

    float dA0 = qA0*kA0a + qA1*kA0b;
    float dA1 = qA0*kA1a + qA1*kA1b;
    float dB0 = qB0*kB0a + qB1*kB0b;
    float dB1 = qB0*kB1a + qB1*kB1b;
    #pragma unroll
    for (int o = 16; o > 0; o >>= 1) {
        dA0 += __shfl_xor_sync(0xffffffffu, dA0, o);
        dA1 += __shfl_xor_sync(0xffffffffu, dA1, o);
        dB0 += __shfl_xor_sync(0xffffffffu, dB0, o);
        dB1 += __shfl_xor_sync(0xffffffffu, dB1, o);
    }
    const float scale = 0.125f;
    dA0 *= scale; dA1 *= scale; dB0 *= scale; dB1 *= scale;
    float mA = fmaxf(dA0, dA1), mB = fmaxf(dB0, dB1);
    float eA0 = __expf(dA0 - mA), eA1 = __expf(dA1 - mA);
    float eB0 = __expf(dB0 - mB), eB1 = __expf(dB1 - mB);
    float iA = 1.0f / (eA0 + eA1), iB = 1.0f / (eB0 + eB1);
    float aA0 = eA0 * iA, aA1 = eA1 * iA;
    float aB0 = eB0 * iB, aB1 = eB1 * iB;

    float rAa = aA0*vA0a + aA1*vA1a, rAb = aA0*vA0b + aA1*vA1b;
    float rBa = aB0*vB0a + aB1*vB1a, rBb = aB0*vB0b + aB1*vB1b;

    bf16 hh, ll;
    size_t ob = (size_t)bn * INNERc;
    bsplit(rAa, hh, ll); aoh[ob + h0*DHd + lane]      = hh; aol[ob + h0*DHd + lane]      = ll;
    bsplit(rAb, hh, ll); aoh[ob + h0*DHd + lane + 32] = hh; aol[ob + h0*DHd + lane + 32] = ll;
    bsplit(rBa, hh, ll); aoh[ob + h1*DHd + lane]      = hh; aol[ob + h1*DHd + lane]      = ll;
    bsplit(rBb, hh, ll); aoh[ob + h1*DHd + lane + 32] = hh; aol[ob + h1*DHd + lane + 32] = ll;
}

// ================= launch =================
static void launch_cfg(cudaLaunchConfig_t* cfg, cudaLaunchAttribute* at,
                       dim3 g, dim3 b, size_t sm){
    memset(cfg, 0, sizeof(*cfg));
    at->id = cudaLaunchAttributeProgrammaticStreamSerialization;
    at->val.programmaticStreamSerializationAllowed = 1;
    cfg->gridDim = g; cfg->blockDim = b; cfg->dynamicSmemBytes = sm;
    cfg->stream = 0; cfg->attrs = at; cfg->numAttrs = 1;
}

extern "C" void kernel_launch(void* const* d_in, const int* in_sizes, int n_in,
                              void* d_out, int out_size) {
    const float* x     = (const float*)d_in[0];
    const float* px    = (const float*)d_in[1];
    const float* lnqg  = (const float*)d_in[2];
    const float* lnqb  = (const float*)d_in[3];
    const float* lnkg  = (const float*)d_in[4];
    const float* lnkb  = (const float*)d_in[5];
    const float* lnvg  = (const float*)d_in[6];
    const float* lnvb  = (const float*)d_in[7];
    const float* Wq    = (const float*)d_in[8];
    const float* Wk    = (const float*)d_in[9];
    const float* bk    = (const float*)d_in[10];
    const float* Wv    = (const float*)d_in[11];
    const float* bv    = (const float*)d_in[12];
    const float* Woff  = (const float*)d_in[13];
    const float* boff  = (const float*)d_in[14];
    const float* Wout  = (const float*)d_in[15];
    const float* bout  = (const float*)d_in[16];

    bf16 *qlnh,*qlnl,*nh,*nl,*aoh,*aol;
    bf16 *wqTh,*wqTl,*wkvTh,*wkvTl,*wouth,*woutl,*w2h,*w2l;
    float *qb,*kvb,*biasq,*biaskv,*bias2,*offb;
    cudaGetSymbolAddress((void**)&qlnh, g_qlnh);
    cudaGetSymbolAddress((void**)&qlnl, g_qlnl);
    cudaGetSymbolAddress((void**)&qb,   g_q);
    cudaGetSymbolAddress((void**)&nh,   g_nh);
    cudaGetSymbolAddress((void**)&nl,   g_nl);
    cudaGetSymbolAddress((void**)&kvb,  g_kv);
    cudaGetSymbolAddress((void**)&aoh,  g_aoh);
    cudaGetSymbolAddress((void**)&aol,  g_aol);
    cudaGetSymbolAddress((void**)&wqTh, g_wqTh);
    cudaGetSymbolAddress((void**)&wqTl, g_wqTl);
    cudaGetSymbolAddress((void**)&wkvTh, g_wkvTh);
    cudaGetSymbolAddress((void**)&wkvTl, g_wkvTl);
    cudaGetSymbolAddress((void**)&wouth, g_wouth);
    cudaGetSymbolAddress((void**)&woutl, g_woutl);
    cudaGetSymbolAddress((void**)&biasq,  g_biasq);
    cudaGetSymbolAddress((void**)&biaskv, g_biaskv);
    cudaGetSymbolAddress((void**)&w2h,  g_w2h);
    cudaGetSymbolAddress((void**)&w2l,  g_w2l);
    cudaGetSymbolAddress((void**)&bias2, g_bias2);
    cudaGetSymbolAddress((void**)&offb,  g_offb);

    cudaFuncSetAttribute((const void*)bf16x3_gemm<1,128>, cudaFuncAttributeMaxDynamicSharedMemorySize, GEMM_SMEM_128);
    cudaFuncSetAttribute((const void*)bf16x3_gemm<1,64>,  cudaFuncAttributeMaxDynamicSharedMemorySize, GEMM_SMEM_64);

    float* out_main = (float*)d_out;
    float* out_off  = out_main + (size_t)MQ * DIMc;

    cudaLaunchConfig_t cfg; cudaLaunchAttribute at;

    // 0: merged prep + LN
    launch_cfg(&cfg, &at, dim3(PREP_LN_BLOCKS), dim3(256), 0);
    cudaLaunchKernelEx(&cfg, prep_ln_kernel, x, px,
                       Wq, lnqg, lnqb, Wk, lnkg, lnkb, bk, Wv, lnvg, lnvb, bv, Wout,
                       qlnh, qlnl, nh, nl, wqTh, wqTl, wkvTh, wkvTl, wouth, woutl,
                       biasq, biaskv);

    // 1: fold offset weights (needs biasq from prep)
    launch_cfg(&cfg, &at, dim3(PREP2_BLOCKS), dim3(256), 0);
    cudaLaunchKernelEx(&cfg, prep2_kernel, Wq, lnqg, Woff, boff,
                       (const float*)biasq, w2h, w2l, bias2);

    // 2: kv = nrm @ [foldedWk | foldedWv] + biaskv
    launch_cfg(&cfg, &at, dim3(2*INNERc/128, MKV/128), dim3(256), GEMM_SMEM_128);
    cudaLaunchKernelEx(&cfg, bf16x3_gemm<1,128>,
                       (const bf16*)nh, (const bf16*)nl, (const bf16*)wkvTh, (const bf16*)wkvTl,
                       (const float*)biaskv, kvb, (int)(2*INNERc), (int)DIMc);

    // 3: q = nrm_q @ foldedWq + biasq
    launch_cfg(&cfg, &at, dim3(INNERc/128, MQ/128), dim3(256), GEMM_SMEM_128);
    cudaLaunchKernelEx(&cfg, bf16x3_gemm<1,128>,
                       (const bf16*)qlnh, (const bf16*)qlnl, (const bf16*)wqTh, (const bf16*)wqTl,
                       (const float*)biasq, qb, (int)INNERc, (int)INNERc);

    // 4: offsets = nrm_q @ W2 + bias2   (tensor cores, Ntot=64 padded)
    launch_cfg(&cfg, &at, dim3(1, MQ/128), dim3(256), GEMM_SMEM_64);
    cudaLaunchKernelEx(&cfg, bf16x3_gemm<1,64>,
                       (const bf16*)qlnh, (const bf16*)qlnl, (const bf16*)w2h, (const bf16*)w2l,
                       (const float*)bias2, offb, (int)64, (int)INNERc);

    // 5: attention (also writes transposed offsets output)
    launch_cfg(&cfg, &at, dim3((MQ*4)/8), dim3(256), 0);
    cudaLaunchKernelEx(&cfg, attn_kernel, (const float*)qb, (const float*)kvb,
                       (const float*)offb, out_off, aoh, aol);

    // 6: out = ao @ Wout^T + bout
    launch_cfg(&cfg, &at, dim3(DIMc/64, MQ/128), dim3(256), GEMM_SMEM_64);
    cudaLaunchKernelEx(&cfg, bf16x3_gemm<1,64>,
                       (const bf16*)aoh, (const bf16*)aol, (const bf16*)wouth, (const bf16*)woutl,
                       (const float*)bout, out_main, (int)DIMc, (int)INNERc);
}